// round 4
// baseline (speedup 1.0000x reference)
#include <cuda_runtime.h>
#include <math.h>

// ---------------- problem dims ----------------
#define B2   2
#define S48  110592   // 48^3
#define S24  13824    // 24^3
#define S12  1728     // 12^3
#define EE   768
#define EQ   192
#define NH   12
#define HD   64
#define NTOK (B2*S12)     // 3456
#define KK2  1536         // conv2 inner dim (192*8)

// ---------------- scratch (__device__ globals; no runtime alloc) ----------------
__device__ float g_lnskip[B2*6*S48];
__device__ float g_lnx   [B2*6*S48];
__device__ float g_h1b   [NTOK*KK2];             // conv1 out in patch-major layout
__device__ float g_q     [NTOK*EE];
__device__ float g_k     [NTOK*EE];
__device__ float g_v     [NTOK*EE];
__device__ float g_Wt    [KK2*EE];               // transposed weight scratch (reused)
__device__ float g_S     [(size_t)B2*NH*S12*S12];// attention scores, ~287MB
__device__ float g_att   [NTOK*EE];
__device__ float g_deb   [NTOK*KK2];

// ---------------- block reductions ----------------
__device__ __forceinline__ float blk_sum(float v, float* sh) {
    int lane = threadIdx.x & 31;
#pragma unroll
    for (int o = 16; o; o >>= 1) v += __shfl_xor_sync(0xffffffffu, v, o);
    __syncthreads();
    if (lane == 0) sh[threadIdx.x >> 5] = v;
    __syncthreads();
    int nw = blockDim.x >> 5;
    v = (lane < nw) ? sh[lane] : 0.f;
#pragma unroll
    for (int o = 16; o; o >>= 1) v += __shfl_xor_sync(0xffffffffu, v, o);
    return v;
}
__device__ __forceinline__ float blk_max(float v, float* sh) {
    int lane = threadIdx.x & 31;
#pragma unroll
    for (int o = 16; o; o >>= 1) v = fmaxf(v, __shfl_xor_sync(0xffffffffu, v, o));
    __syncthreads();
    if (lane == 0) sh[threadIdx.x >> 5] = v;
    __syncthreads();
    int nw = blockDim.x >> 5;
    v = (lane < nw) ? sh[lane] : -3.4e38f;
#pragma unroll
    for (int o = 16; o; o >>= 1) v = fmaxf(v, __shfl_xor_sync(0xffffffffu, v, o));
    return v;
}

// robust fp32 sincos: Cody-Waite reduce mod 2pi, then accurate-range trig.
__device__ __forceinline__ void rope_trig(float f, float& cs, float& sn) {
    float n = rintf(f * 0.15915494309189535f);      // f / (2pi)
    float r = fmaf(-n, 6.28125f, f);                // 2pi = 6.28125 + 1.9353072e-3 (hi exact)
    r = fmaf(-n, 1.9353071795864769e-3f, r);
    cs = cosf(r);
    sn = sinf(r);
}

// ---------------- LN over 6 channels (channels-first) ----------------
__global__ void k_ln6(const float* __restrict__ in, const float* __restrict__ w,
                      const float* __restrict__ bb, float* __restrict__ out) {
    int p = blockIdx.x * blockDim.x + threadIdx.x;
    if (p >= B2 * S48) return;
    int bn = p / S48, sp = p - bn * S48;
    const float* base = in + (size_t)bn * 6 * S48 + sp;
    float v[6], u = 0.f;
#pragma unroll
    for (int c = 0; c < 6; c++) { v[c] = base[(size_t)c * S48]; u += v[c]; }
    u *= (1.f / 6.f);
    float s = 0.f;
#pragma unroll
    for (int c = 0; c < 6; c++) { float d = v[c] - u; s += d * d; }
    s *= (1.f / 6.f);
    float r = rsqrtf(s + 1e-6f);
    float* ob = out + (size_t)bn * 6 * S48 + sp;
#pragma unroll
    for (int c = 0; c < 6; c++) ob[(size_t)c * S48] = (v[c] - u) * r * w[c] + bb[c];
}

// ---------------- conv2s2 (6->192) fused LN192+GELU; writes patch-major ----------------
__global__ void k_conv1(const float* __restrict__ in, const float* __restrict__ W,
                        const float* __restrict__ g, const float* __restrict__ bb,
                        float* __restrict__ out) {
    __shared__ float patch[48];
    __shared__ float sh[32];
    int bid = blockIdx.x;
    int bn = bid / S24, pos = bid - bn * S24;
    int h = pos / 576, w = (pos / 24) % 24, d = pos % 24;
    int t = threadIdx.x; // 192
    if (t < 48) {
        int ic = t >> 3, kpq = t & 7;
        int k = kpq >> 2, pp = (kpq >> 1) & 1, q = kpq & 1;
        patch[t] = in[(((size_t)(bn * 6 + ic) * 48 + 2 * h + k) * 48 + 2 * w + pp) * 48 + 2 * d + q];
    }
    __syncthreads();
    float acc = 0.f;
    const float* wr = W + t * 48;
#pragma unroll
    for (int j = 0; j < 48; j++) acc += patch[j] * __ldg(&wr[j]);
    float u = blk_sum(acc, sh) * (1.f / 192.f);
    float dd = acc - u;
    float var = blk_sum(dd * dd, sh) * (1.f / 192.f);
    float xn = dd * rsqrtf(var + 1e-6f) * g[t] + bb[t];
    float ge = xn * normcdff(xn);   // exact GELU
    int n1 = (h >> 1) * 144 + (w >> 1) * 12 + (d >> 1);
    int par = (h & 1) * 4 + (w & 1) * 2 + (d & 1);
    out[(size_t)(bn * S12 + n1) * KK2 + t * 8 + par] = ge;
}

// ---------------- generic 64x64 tile SGEMM: C[n][m] = sum_k A[n][k]*B[k][m] ----------------
__global__ void k_gemm64(const float* __restrict__ A, const float* __restrict__ B,
                         float* __restrict__ C, int K, int lda, int ldb, int ldc) {
    __shared__ float As[16][64];
    __shared__ float Bs[16][64];
    int tid = threadIdx.x;
    int tx = tid & 15, ty = tid >> 4;
    int n0 = blockIdx.y * 64, m0 = blockIdx.x * 64;
    int lr = tid >> 2, lc = (tid & 3) * 4;
    int br = tid >> 4, bc = (tid & 15) * 4;
    const float* Ap = A + (size_t)(n0 + lr) * lda + lc;
    const float* Bp = B + (size_t)br * ldb + m0 + bc;
    float acc[4][4] = {};
    for (int k0 = 0; k0 < K; k0 += 16) {
        float4 a  = *(const float4*)(Ap + k0);
        float4 bv = *(const float4*)(Bp + (size_t)k0 * ldb);
        __syncthreads();
        As[lc + 0][lr] = a.x; As[lc + 1][lr] = a.y; As[lc + 2][lr] = a.z; As[lc + 3][lr] = a.w;
        *(float4*)&Bs[br][bc] = bv;
        __syncthreads();
#pragma unroll
        for (int kk = 0; kk < 16; kk++) {
            float4 av = *(const float4*)&As[kk][ty * 4];
            float4 bw = *(const float4*)&Bs[kk][tx * 4];
            float aa[4] = {av.x, av.y, av.z, av.w};
            float bbv[4] = {bw.x, bw.y, bw.z, bw.w};
#pragma unroll
            for (int i = 0; i < 4; i++)
#pragma unroll
                for (int j = 0; j < 4; j++) acc[i][j] += aa[i] * bbv[j];
        }
    }
#pragma unroll
    for (int i = 0; i < 4; i++) {
        float4 o = make_float4(acc[i][0], acc[i][1], acc[i][2], acc[i][3]);
        *(float4*)&C[(size_t)(n0 + ty * 4 + i) * ldc + m0 + tx * 4] = o;
    }
}

// ---------------- LN over 768 (+optional RoPE), in place, token-major rows ----------------
__global__ void k_ln768(float* __restrict__ X, const float* __restrict__ w,
                        const float* __restrict__ bb, int doRope) {
    __shared__ float s[768];
    __shared__ float sh[32];
    int n = blockIdx.x, tid = threadIdx.x;
    float* row = X + (size_t)n * 768;
    float partial = 0.f;
#pragma unroll
    for (int it = 0; it < 3; it++) { int j = tid + it * 256; float v = row[j]; s[j] = v; partial += v; }
    float u = blk_sum(partial, sh) * (1.f / 768.f);
    float p2 = 0.f;
#pragma unroll
    for (int it = 0; it < 3; it++) { int j = tid + it * 256; float dd = s[j] - u; p2 += dd * dd; }
    float var = blk_sum(p2, sh) * (1.f / 768.f);
    float rinv = rsqrtf(var + 1e-6f);
#pragma unroll
    for (int it = 0; it < 3; it++) { int j = tid + it * 256; s[j] = (s[j] - u) * rinv * w[j] + bb[j]; }
    __syncthreads();
    if (doRope) {
        int l = n % S12;
#pragma unroll
        for (int it = 0; it < 3; it++) {
            int j = tid + it * 256;
            int jm = (j < 384) ? j : j - 384;          // FIXED: 384 is not a power of two
            float inv = exp2f(-(float)jm * (13.287712379549449f / 384.f)); // 10000^(-jm/384)
            float f = (float)l * inv;
            float cs, sn;
            rope_trig(f, cs, sn);
            float rot = (j < 384) ? -s[j + 384] : s[j - 384];
            row[j] = s[j] * cs + rot * sn;
        }
    } else {
#pragma unroll
        for (int it = 0; it < 3; it++) { int j = tid + it * 256; row[j] = s[j]; }
    }
}

// ---------------- attention scores: S[z][i][j] = Q_i . K_j (per batch*head) ----------------
__global__ void k_scores(const float* __restrict__ Q, const float* __restrict__ Km,
                         float* __restrict__ S) {
    __shared__ float As[16][64];
    __shared__ float Bs[16][64];
    int z = blockIdx.z, b = z / NH, h = z - b * NH;
    int i0 = blockIdx.y * 64, j0 = blockIdx.x * 64;
    const float* qb = Q + (size_t)b * S12 * EE + h * HD;
    const float* kb = Km + (size_t)b * S12 * EE + h * HD;
    int tid = threadIdx.x;
    int tx = tid & 15, ty = tid >> 4;
    int lr = tid >> 2, lc = (tid & 3) * 4;
    float acc[4][4] = {};
    for (int k0 = 0; k0 < HD; k0 += 16) {
        float4 a  = *(const float4*)&qb[(size_t)(i0 + lr) * EE + k0 + lc];
        float4 bv = *(const float4*)&kb[(size_t)(j0 + lr) * EE + k0 + lc];
        __syncthreads();
        As[lc + 0][lr] = a.x;  As[lc + 1][lr] = a.y;  As[lc + 2][lr] = a.z;  As[lc + 3][lr] = a.w;
        Bs[lc + 0][lr] = bv.x; Bs[lc + 1][lr] = bv.y; Bs[lc + 2][lr] = bv.z; Bs[lc + 3][lr] = bv.w;
        __syncthreads();
#pragma unroll
        for (int kk = 0; kk < 16; kk++) {
            float4 av = *(const float4*)&As[kk][ty * 4];
            float4 bw = *(const float4*)&Bs[kk][tx * 4];
            float aa[4] = {av.x, av.y, av.z, av.w};
            float bbv[4] = {bw.x, bw.y, bw.z, bw.w};
#pragma unroll
            for (int i = 0; i < 4; i++)
#pragma unroll
                for (int j = 0; j < 4; j++) acc[i][j] += aa[i] * bbv[j];
        }
    }
    float* Sz = S + (size_t)z * S12 * S12;
#pragma unroll
    for (int i = 0; i < 4; i++) {
        float4 o = make_float4(acc[i][0], acc[i][1], acc[i][2], acc[i][3]);
        *(float4*)&Sz[(size_t)(i0 + ty * 4 + i) * S12 + j0 + tx * 4] = o;
    }
}

// ---------------- rowwise softmax with scale 1/8 (in place) ----------------
__global__ void k_softmax(float* __restrict__ S) {
    __shared__ float sh[32];
    int row = blockIdx.x;
    float* r = S + (size_t)row * S12;
    int tid = threadIdx.x;
    float vals[7];
    float mx = -3.4e38f;
    for (int i = 0, j = tid; j < S12; j += 256, i++) { float v = r[j]; vals[i] = v; mx = fmaxf(mx, v); }
    mx = blk_max(mx, sh);
    float sum = 0.f;
    for (int i = 0, j = tid; j < S12; j += 256, i++) {
        float e = expf((vals[i] - mx) * 0.125f);
        vals[i] = e; sum += e;
    }
    sum = blk_sum(sum, sh);
    float inv = 1.f / sum;
    for (int i = 0, j = tid; j < S12; j += 256, i++) r[j] = vals[i] * inv;
}

// ---------------- PV GEMM: O[b,h,i,d] -> att[(b*L+i)*768 + d*12+h] ----------------
__global__ void k_pv(const float* __restrict__ S, const float* __restrict__ V,
                     float* __restrict__ O) {
    __shared__ float As[16][64];
    __shared__ float Bs[16][64];
    int z = blockIdx.z, b = z / NH, h = z - b * NH;
    const float* A  = S + (size_t)z * S12 * S12;
    const float* Bm = V + (size_t)b * S12 * EE + h * HD;
    int n0 = blockIdx.y * 64;
    int tid = threadIdx.x, tx = tid & 15, ty = tid >> 4;
    int lr = tid >> 2, lc = (tid & 3) * 4;
    int br = tid >> 4, bc = (tid & 15) * 4;
    float acc[4][4] = {};
    for (int k0 = 0; k0 < S12; k0 += 16) {
        float4 a  = *(const float4*)&A[(size_t)(n0 + lr) * S12 + k0 + lc];
        float4 bv = *(const float4*)&Bm[(size_t)(k0 + br) * EE + bc];
        __syncthreads();
        As[lc + 0][lr] = a.x; As[lc + 1][lr] = a.y; As[lc + 2][lr] = a.z; As[lc + 3][lr] = a.w;
        *(float4*)&Bs[br][bc] = bv;
        __syncthreads();
#pragma unroll
        for (int kk = 0; kk < 16; kk++) {
            float4 av = *(const float4*)&As[kk][ty * 4];
            float4 bw = *(const float4*)&Bs[kk][tx * 4];
            float aa[4] = {av.x, av.y, av.z, av.w};
            float bbv[4] = {bw.x, bw.y, bw.z, bw.w};
#pragma unroll
            for (int i = 0; i < 4; i++)
#pragma unroll
                for (int j = 0; j < 4; j++) acc[i][j] += aa[i] * bbv[j];
        }
    }
#pragma unroll
    for (int i = 0; i < 4; i++)
#pragma unroll
        for (int j = 0; j < 4; j++)
            O[(size_t)(b * S12 + n0 + ty * 4 + i) * EE + (tx * 4 + j) * NH + h] = acc[i][j];
}

// ---------------- weight transposes ----------------
__global__ void k_transW2(const float* __restrict__ in, float* __restrict__ out) {
    int idx = blockIdx.x * blockDim.x + threadIdx.x;
    if (idx >= EE * KK2) return;
    int o = idx / KK2, r = idx - o * KK2;
    out[(size_t)r * EE + o] = in[idx];
}
__global__ void k_transWd(const float* __restrict__ in, float* __restrict__ out) {
    int idx = blockIdx.x * blockDim.x + threadIdx.x;
    if (idx >= EE * KK2) return;
    int i = idx / KK2, rest = idx - i * KK2;
    int o = rest >> 3, r = rest & 7;  // in: [i][o][r]
    out[(size_t)i * KK2 + r * 192 + o] = in[idx];
}

// ---------------- LN192 + GELU rowwise (debed intermediate), in place ----------------
__global__ void k_ln192gelu(float* __restrict__ X, const float* __restrict__ g,
                            const float* __restrict__ bb) {
    __shared__ float sh[32];
    int n = blockIdx.x, t = threadIdx.x; // 192 threads
    float* row = X + (size_t)n * 192;
    float v = row[t];
    float u = blk_sum(v, sh) * (1.f / 192.f);
    float dd = v - u;
    float var = blk_sum(dd * dd, sh) * (1.f / 192.f);
    float xn = dd * rsqrtf(var + 1e-6f) * g[t] + bb[t];
    row[t] = xn * normcdff(xn);
}

// ---------------- final convT2s2 (192->6) + bias + residual ----------------
__global__ void k_debed2(const float* __restrict__ glo, const float* __restrict__ W,
                         const float* __restrict__ bias, const float* __restrict__ res,
                         float* __restrict__ out) {
    __shared__ float row[192];
    int bid = blockIdx.x;
    int bn = bid / S24, pos = bid - bn * S24;
    int H = pos / 576, Wp = (pos / 24) % 24, D = pos % 24;
    int n1 = (H >> 1) * 144 + (Wp >> 1) * 12 + (D >> 1);
    int rr = (H & 1) * 4 + (Wp & 1) * 2 + (D & 1);
    const float* rp = glo + (size_t)(bn * S12 + n1) * KK2 + rr * 192;
    int t = threadIdx.x; // 64
    for (int j = t; j < 192; j += 64) row[j] = rp[j];
    __syncthreads();
    if (t < 48) {
        int c = t >> 3, r2 = t & 7;
        float acc = 0.f;
#pragma unroll
        for (int o = 0; o < 192; o++) acc += row[o] * __ldg(&W[o * 48 + c * 8 + r2]);
        int Hf = 2 * H + (r2 >> 2), Wf = 2 * Wp + ((r2 >> 1) & 1), Df = 2 * D + (r2 & 1);
        size_t oi = (((size_t)(bn * 6 + c) * 48 + Hf) * 48 + Wf) * 48 + Df;
        out[oi] = acc + bias[c] + res[oi];
    }
}

// ---------------- launch ----------------
extern "C" void kernel_launch(void* const* d_in, const int* in_sizes, int n_in,
                              void* d_out, int out_size) {
    const float* x     = (const float*)d_in[0];
    const float* skip  = (const float*)d_in[1];
    const float* o_tw1 = (const float*)d_in[20];
    const float* o_g   = (const float*)d_in[21];
    const float* o_b   = (const float*)d_in[22];
    const float* o_tw2 = (const float*)d_in[23];
    const float* o_tb2 = (const float*)d_in[24];
    const float* ns_w  = (const float*)d_in[25];
    const float* ns_b  = (const float*)d_in[26];
    const float* nx_w  = (const float*)d_in[27];
    const float* nx_b  = (const float*)d_in[28];
    const float* no_w  = (const float*)d_in[29];
    const float* no_b  = (const float*)d_in[30];
    float* out = (float*)d_out;

    float *lnskip, *lnx, *h1b, *q, *k, *v, *Wt, *S, *att, *deb;
    cudaGetSymbolAddress((void**)&lnskip, g_lnskip);
    cudaGetSymbolAddress((void**)&lnx,    g_lnx);
    cudaGetSymbolAddress((void**)&h1b,    g_h1b);
    cudaGetSymbolAddress((void**)&q,      g_q);
    cudaGetSymbolAddress((void**)&k,      g_k);
    cudaGetSymbolAddress((void**)&v,      g_v);
    cudaGetSymbolAddress((void**)&Wt,     g_Wt);
    cudaGetSymbolAddress((void**)&S,      g_S);
    cudaGetSymbolAddress((void**)&att,    g_att);
    cudaGetSymbolAddress((void**)&deb,    g_deb);

    k_ln6<<<(B2 * S48 + 255) / 256, 256>>>(skip, ns_w, ns_b, lnskip);
    k_ln6<<<(B2 * S48 + 255) / 256, 256>>>(x,    nx_w, nx_b, lnx);

    const float* stem_in[3] = {lnskip, lnx, lnx};
    float* stem_out[3] = {q, k, v};
    int rope[3] = {1, 1, 0};
    for (int si = 0; si < 3; si++) {
        int base = 2 + si * 6;
        const float* w1 = (const float*)d_in[base + 0];
        const float* g1 = (const float*)d_in[base + 1];
        const float* b1 = (const float*)d_in[base + 2];
        const float* w2 = (const float*)d_in[base + 3];
        const float* g2 = (const float*)d_in[base + 4];
        const float* b2 = (const float*)d_in[base + 5];
        k_transW2<<<(EE * KK2 + 255) / 256, 256>>>(w2, Wt);
        k_conv1<<<B2 * S24, 192>>>(stem_in[si], w1, g1, b1, h1b);
        dim3 gg(EE / 64, NTOK / 64);
        k_gemm64<<<gg, 256>>>(h1b, Wt, stem_out[si], KK2, KK2, EE, EE);
        k_ln768<<<NTOK, 256>>>(stem_out[si], g2, b2, rope[si]);
    }

    k_scores<<<dim3(27, 27, 24), 256>>>(q, k, S);
    k_softmax<<<B2 * NH * S12, 256>>>(S);
    k_pv<<<dim3(1, 27, 24), 256>>>(S, v, att);

    k_ln768<<<NTOK, 256>>>(att, no_w, no_b, 0);
    k_transWd<<<(EE * KK2 + 255) / 256, 256>>>(o_tw1, Wt);
    dim3 gd(KK2 / 64, NTOK / 64);
    k_gemm64<<<gd, 256>>>(att, Wt, deb, EE, EE, KK2, KK2);
    k_ln192gelu<<<NTOK * 8, 192>>>(deb, o_g, o_b);
    k_debed2<<<B2 * S24, 64>>>(deb, o_tw2, o_tb2, skip, out);
}

// round 5
// speedup vs baseline: 1.5922x; 1.5922x over previous
#include <cuda_runtime.h>
#include <math.h>

// ---------------- problem dims ----------------
#define B2   2
#define S48  110592   // 48^3
#define S24  13824    // 24^3
#define S12  1728     // 12^3
#define EE   768
#define NH   12
#define HD   64
#define NTOK (B2*S12)     // 3456
#define KK2  1536         // conv2 inner dim (192*8)
#define NPATCH (B2*S24)   // 27648 patch rows (= NTOK*8)

// ---------------- scratch (__device__ globals; no runtime alloc) ----------------
__device__ float g_patchs[NPATCH*48];            // skip patches (LN6 applied)
__device__ float g_patchx[NPATCH*48];            // x patches (LN6 applied)
__device__ float g_h1b   [NPATCH*192];           // conv1 out rows (token*8+par)x192 == conv2 A [3456x1536]
__device__ float g_q     [NTOK*EE];
__device__ float g_k     [NTOK*EE];
__device__ float g_v     [NTOK*EE];
__device__ float g_Wt    [KK2*EE];               // transposed weight scratch (reused)
__device__ float g_S     [(size_t)B2*NH*S12*S12];// attention scores, ~287MB
__device__ float g_att   [NTOK*EE];
__device__ float g_deb   [NTOK*KK2];

// ---------------- block reductions ----------------
__device__ __forceinline__ float blk_sum(float v, float* sh) {
    int lane = threadIdx.x & 31;
#pragma unroll
    for (int o = 16; o; o >>= 1) v += __shfl_xor_sync(0xffffffffu, v, o);
    __syncthreads();
    if (lane == 0) sh[threadIdx.x >> 5] = v;
    __syncthreads();
    int nw = blockDim.x >> 5;
    v = (lane < nw) ? sh[lane] : 0.f;
#pragma unroll
    for (int o = 16; o; o >>= 1) v += __shfl_xor_sync(0xffffffffu, v, o);
    return v;
}
__device__ __forceinline__ float blk_max(float v, float* sh) {
    int lane = threadIdx.x & 31;
#pragma unroll
    for (int o = 16; o; o >>= 1) v = fmaxf(v, __shfl_xor_sync(0xffffffffu, v, o));
    __syncthreads();
    if (lane == 0) sh[threadIdx.x >> 5] = v;
    __syncthreads();
    int nw = blockDim.x >> 5;
    v = (lane < nw) ? sh[lane] : -3.4e38f;
#pragma unroll
    for (int o = 16; o; o >>= 1) v = fmaxf(v, __shfl_xor_sync(0xffffffffu, v, o));
    return v;
}

// robust fp32 sincos: Cody-Waite reduce mod 2pi, then accurate-range trig.
__device__ __forceinline__ void rope_trig(float f, float& cs, float& sn) {
    float n = rintf(f * 0.15915494309189535f);      // f / (2pi)
    float r = fmaf(-n, 6.28125f, f);                // 2pi = 6.28125 + 1.9353072e-3 (hi exact)
    r = fmaf(-n, 1.9353071795864769e-3f, r);
    cs = cosf(r);
    sn = sinf(r);
}

// ---------------- fused LN6 + patch gather ----------------
// one thread per (patch position, kpq). Writes patch rows ordered q = token*8 + par.
__global__ void k_patch(const float* __restrict__ in, const float* __restrict__ w,
                        const float* __restrict__ bb, float* __restrict__ out) {
    int id = blockIdx.x * blockDim.x + threadIdx.x;
    if (id >= NPATCH * 8) return;
    int kpq = id & 7;
    int p = id >> 3;                    // 0..27647
    int bn = p / S24, pos = p - bn * S24;
    int h = pos / 576, w24 = (pos / 24) % 24, d = pos % 24;
    int k = kpq >> 2, pp = (kpq >> 1) & 1, qq = kpq & 1;
    size_t sp = ((size_t)(2 * h + k) * 48 + 2 * w24 + pp) * 48 + 2 * d + qq;
    const float* base = in + (size_t)bn * 6 * S48 + sp;
    float v[6], u = 0.f;
#pragma unroll
    for (int c = 0; c < 6; c++) { v[c] = base[(size_t)c * S48]; u += v[c]; }
    u *= (1.f / 6.f);
    float s = 0.f;
#pragma unroll
    for (int c = 0; c < 6; c++) { float dd = v[c] - u; s += dd * dd; }
    s *= (1.f / 6.f);
    float r = rsqrtf(s + 1e-6f);
    int token = bn * S12 + (h >> 1) * 144 + (w24 >> 1) * 12 + (d >> 1);
    int par = (h & 1) * 4 + (w24 & 1) * 2 + (d & 1);
    float* ob = out + ((size_t)token * 8 + par) * 48 + kpq;
#pragma unroll
    for (int c = 0; c < 6; c++) ob[c * 8] = (v[c] - u) * r * w[c] + bb[c];
}

// ---------------- generic 64x64 tile SGEMM: C[n][m] = sum_k A[n][k]*B[k][m] ----------------
__global__ void k_gemm64(const float* __restrict__ A, const float* __restrict__ B,
                         float* __restrict__ C, int K, int lda, int ldb, int ldc) {
    __shared__ float As[16][64];
    __shared__ float Bs[16][64];
    int tid = threadIdx.x;
    int tx = tid & 15, ty = tid >> 4;
    int n0 = blockIdx.y * 64, m0 = blockIdx.x * 64;
    int lr = tid >> 2, lc = (tid & 3) * 4;
    int br = tid >> 4, bc = (tid & 15) * 4;
    const float* Ap = A + (size_t)(n0 + lr) * lda + lc;
    const float* Bp = B + (size_t)br * ldb + m0 + bc;
    float acc[4][4] = {};
    for (int k0 = 0; k0 < K; k0 += 16) {
        float4 a  = *(const float4*)(Ap + k0);
        float4 bv = *(const float4*)(Bp + (size_t)k0 * ldb);
        __syncthreads();
        As[lc + 0][lr] = a.x; As[lc + 1][lr] = a.y; As[lc + 2][lr] = a.z; As[lc + 3][lr] = a.w;
        *(float4*)&Bs[br][bc] = bv;
        __syncthreads();
#pragma unroll
        for (int kk = 0; kk < 16; kk++) {
            float4 av = *(const float4*)&As[kk][ty * 4];
            float4 bw = *(const float4*)&Bs[kk][tx * 4];
            float aa[4] = {av.x, av.y, av.z, av.w};
            float bbv[4] = {bw.x, bw.y, bw.z, bw.w};
#pragma unroll
            for (int i = 0; i < 4; i++)
#pragma unroll
                for (int j = 0; j < 4; j++) acc[i][j] += aa[i] * bbv[j];
        }
    }
#pragma unroll
    for (int i = 0; i < 4; i++) {
        float4 o = make_float4(acc[i][0], acc[i][1], acc[i][2], acc[i][3]);
        *(float4*)&C[(size_t)(n0 + ty * 4 + i) * ldc + m0 + tx * 4] = o;
    }
}

// ---------------- LN over 768 (+optional RoPE), in place, token-major rows ----------------
__global__ void k_ln768(float* __restrict__ X, const float* __restrict__ w,
                        const float* __restrict__ bb, int doRope) {
    __shared__ float s[768];
    __shared__ float sh[32];
    int n = blockIdx.x, tid = threadIdx.x;
    float* row = X + (size_t)n * 768;
    float partial = 0.f;
#pragma unroll
    for (int it = 0; it < 3; it++) { int j = tid + it * 256; float v = row[j]; s[j] = v; partial += v; }
    float u = blk_sum(partial, sh) * (1.f / 768.f);
    float p2 = 0.f;
#pragma unroll
    for (int it = 0; it < 3; it++) { int j = tid + it * 256; float dd = s[j] - u; p2 += dd * dd; }
    float var = blk_sum(p2, sh) * (1.f / 768.f);
    float rinv = rsqrtf(var + 1e-6f);
#pragma unroll
    for (int it = 0; it < 3; it++) { int j = tid + it * 256; s[j] = (s[j] - u) * rinv * w[j] + bb[j]; }
    __syncthreads();
    if (doRope) {
        int l = n % S12;
#pragma unroll
        for (int it = 0; it < 3; it++) {
            int j = tid + it * 256;
            int jm = (j < 384) ? j : j - 384;
            float inv = exp2f(-(float)jm * (13.287712379549449f / 384.f)); // 10000^(-jm/384)
            float f = (float)l * inv;
            float cs, sn;
            rope_trig(f, cs, sn);
            float rot = (j < 384) ? -s[j + 384] : s[j - 384];
            row[j] = s[j] * cs + rot * sn;
        }
    } else {
#pragma unroll
        for (int it = 0; it < 3; it++) { int j = tid + it * 256; row[j] = s[j]; }
    }
}

// ---------------- attention scores: S[z][i][j] = Q_i . K_j (per batch*head) ----------------
__global__ void k_scores(const float* __restrict__ Q, const float* __restrict__ Km,
                         float* __restrict__ S) {
    __shared__ float As[16][64];
    __shared__ float Bs[16][64];
    int z = blockIdx.z, b = z / NH, h = z - b * NH;
    int i0 = blockIdx.y * 64, j0 = blockIdx.x * 64;
    const float* qb = Q + (size_t)b * S12 * EE + h * HD;
    const float* kb = Km + (size_t)b * S12 * EE + h * HD;
    int tid = threadIdx.x;
    int tx = tid & 15, ty = tid >> 4;
    int lr = tid >> 2, lc = (tid & 3) * 4;
    float acc[4][4] = {};
    for (int k0 = 0; k0 < HD; k0 += 16) {
        float4 a  = *(const float4*)&qb[(size_t)(i0 + lr) * EE + k0 + lc];
        float4 bv = *(const float4*)&kb[(size_t)(j0 + lr) * EE + k0 + lc];
        __syncthreads();
        As[lc + 0][lr] = a.x;  As[lc + 1][lr] = a.y;  As[lc + 2][lr] = a.z;  As[lc + 3][lr] = a.w;
        Bs[lc + 0][lr] = bv.x; Bs[lc + 1][lr] = bv.y; Bs[lc + 2][lr] = bv.z; Bs[lc + 3][lr] = bv.w;
        __syncthreads();
#pragma unroll
        for (int kk = 0; kk < 16; kk++) {
            float4 av = *(const float4*)&As[kk][ty * 4];
            float4 bw = *(const float4*)&Bs[kk][tx * 4];
            float aa[4] = {av.x, av.y, av.z, av.w};
            float bbv[4] = {bw.x, bw.y, bw.z, bw.w};
#pragma unroll
            for (int i = 0; i < 4; i++)
#pragma unroll
                for (int j = 0; j < 4; j++) acc[i][j] += aa[i] * bbv[j];
        }
    }
    float* Sz = S + (size_t)z * S12 * S12;
#pragma unroll
    for (int i = 0; i < 4; i++) {
        float4 o = make_float4(acc[i][0], acc[i][1], acc[i][2], acc[i][3]);
        *(float4*)&Sz[(size_t)(i0 + ty * 4 + i) * S12 + j0 + tx * 4] = o;
    }
}

// ---------------- rowwise softmax with scale 1/8 (in place) ----------------
__global__ void k_softmax(float* __restrict__ S) {
    __shared__ float sh[32];
    int row = blockIdx.x;
    float* r = S + (size_t)row * S12;
    int tid = threadIdx.x;
    float vals[7];
    float mx = -3.4e38f;
    for (int i = 0, j = tid; j < S12; j += 256, i++) { float v = r[j]; vals[i] = v; mx = fmaxf(mx, v); }
    mx = blk_max(mx, sh);
    float sum = 0.f;
    for (int i = 0, j = tid; j < S12; j += 256, i++) {
        float e = expf((vals[i] - mx) * 0.125f);
        vals[i] = e; sum += e;
    }
    sum = blk_sum(sum, sh);
    float inv = 1.f / sum;
    for (int i = 0, j = tid; j < S12; j += 256, i++) r[j] = vals[i] * inv;
}

// ---------------- PV GEMM: O[b,h,i,d] -> att[(b*L+i)*768 + d*12+h] ----------------
__global__ void k_pv(const float* __restrict__ S, const float* __restrict__ V,
                     float* __restrict__ O) {
    __shared__ float As[16][64];
    __shared__ float Bs[16][64];
    int z = blockIdx.z, b = z / NH, h = z - b * NH;
    const float* A  = S + (size_t)z * S12 * S12;
    const float* Bm = V + (size_t)b * S12 * EE + h * HD;
    int n0 = blockIdx.y * 64;
    int tid = threadIdx.x, tx = tid & 15, ty = tid >> 4;
    int lr = tid >> 2, lc = (tid & 3) * 4;
    int br = tid >> 4, bc = (tid & 15) * 4;
    float acc[4][4] = {};
    for (int k0 = 0; k0 < S12; k0 += 16) {
        float4 a  = *(const float4*)&A[(size_t)(n0 + lr) * S12 + k0 + lc];
        float4 bv = *(const float4*)&Bm[(size_t)(k0 + br) * EE + bc];
        __syncthreads();
        As[lc + 0][lr] = a.x; As[lc + 1][lr] = a.y; As[lc + 2][lr] = a.z; As[lc + 3][lr] = a.w;
        *(float4*)&Bs[br][bc] = bv;
        __syncthreads();
#pragma unroll
        for (int kk = 0; kk < 16; kk++) {
            float4 av = *(const float4*)&As[kk][ty * 4];
            float4 bw = *(const float4*)&Bs[kk][tx * 4];
            float aa[4] = {av.x, av.y, av.z, av.w};
            float bbv[4] = {bw.x, bw.y, bw.z, bw.w};
#pragma unroll
            for (int i = 0; i < 4; i++)
#pragma unroll
                for (int j = 0; j < 4; j++) acc[i][j] += aa[i] * bbv[j];
        }
    }
#pragma unroll
    for (int i = 0; i < 4; i++)
#pragma unroll
        for (int j = 0; j < 4; j++)
            O[(size_t)(b * S12 + n0 + ty * 4 + i) * EE + (tx * 4 + j) * NH + h] = acc[i][j];
}

// ---------------- weight transposes ----------------
// conv1 weight: w1 [192][48] -> Wt1 [48][192]
__global__ void k_transW1(const float* __restrict__ in, float* __restrict__ out) {
    int idx = blockIdx.x * blockDim.x + threadIdx.x;
    if (idx >= 192 * 48) return;
    int t = idx / 48, j = idx - t * 48;
    out[j * 192 + t] = in[idx];
}
// conv2 weight: w2 [768][192][8] -> Wt2 [(par*192+t)][768]
__global__ void k_transW2(const float* __restrict__ in, float* __restrict__ out) {
    int idx = blockIdx.x * blockDim.x + threadIdx.x;
    if (idx >= EE * KK2) return;
    int o = idx / KK2, rest = idx - o * KK2;
    int t = rest >> 3, par = rest & 7;
    out[(size_t)(par * 192 + t) * EE + o] = in[idx];
}
// debed1 weight: o_tw1 [768][192][8] -> Wt [768][(r*192+o192)]
__global__ void k_transWd(const float* __restrict__ in, float* __restrict__ out) {
    int idx = blockIdx.x * blockDim.x + threadIdx.x;
    if (idx >= EE * KK2) return;
    int i = idx / KK2, rest = idx - i * KK2;
    int o = rest >> 3, r = rest & 7;  // in: [i][o][r]
    out[(size_t)i * KK2 + r * 192 + o] = in[idx];
}

// ---------------- LN192 + GELU rowwise, in place (rows of 192) ----------------
__global__ void k_ln192gelu(float* __restrict__ X, const float* __restrict__ g,
                            const float* __restrict__ bb) {
    __shared__ float sh[32];
    int n = blockIdx.x, t = threadIdx.x; // 192 threads
    float* row = X + (size_t)n * 192;
    float v = row[t];
    float u = blk_sum(v, sh) * (1.f / 192.f);
    float dd = v - u;
    float var = blk_sum(dd * dd, sh) * (1.f / 192.f);
    float xn = dd * rsqrtf(var + 1e-6f) * g[t] + bb[t];
    row[t] = xn * normcdff(xn);
}

// ---------------- final convT2s2 (192->6) + bias + residual ----------------
__global__ void k_debed2(const float* __restrict__ glo, const float* __restrict__ W,
                         const float* __restrict__ bias, const float* __restrict__ res,
                         float* __restrict__ out) {
    __shared__ float row[192];
    int bid = blockIdx.x;
    int bn = bid / S24, pos = bid - bn * S24;
    int H = pos / 576, Wp = (pos / 24) % 24, D = pos % 24;
    int n1 = (H >> 1) * 144 + (Wp >> 1) * 12 + (D >> 1);
    int rr = (H & 1) * 4 + (Wp & 1) * 2 + (D & 1);
    const float* rp = glo + (size_t)(bn * S12 + n1) * KK2 + rr * 192;
    int t = threadIdx.x; // 64
    for (int j = t; j < 192; j += 64) row[j] = rp[j];
    __syncthreads();
    if (t < 48) {
        int c = t >> 3, r2 = t & 7;
        float acc = 0.f;
#pragma unroll
        for (int o = 0; o < 192; o++) acc += row[o] * __ldg(&W[o * 48 + c * 8 + r2]);
        int Hf = 2 * H + (r2 >> 2), Wf = 2 * Wp + ((r2 >> 1) & 1), Df = 2 * D + (r2 & 1);
        size_t oi = (((size_t)(bn * 6 + c) * 48 + Hf) * 48 + Wf) * 48 + Df;
        out[oi] = acc + bias[c] + res[oi];
    }
}

// ---------------- launch ----------------
extern "C" void kernel_launch(void* const* d_in, const int* in_sizes, int n_in,
                              void* d_out, int out_size) {
    const float* x     = (const float*)d_in[0];
    const float* skip  = (const float*)d_in[1];
    const float* o_tw1 = (const float*)d_in[20];
    const float* o_g   = (const float*)d_in[21];
    const float* o_b   = (const float*)d_in[22];
    const float* o_tw2 = (const float*)d_in[23];
    const float* o_tb2 = (const float*)d_in[24];
    const float* ns_w  = (const float*)d_in[25];
    const float* ns_b  = (const float*)d_in[26];
    const float* nx_w  = (const float*)d_in[27];
    const float* nx_b  = (const float*)d_in[28];
    const float* no_w  = (const float*)d_in[29];
    const float* no_b  = (const float*)d_in[30];
    float* out = (float*)d_out;

    float *patchs, *patchx, *h1b, *q, *k, *v, *Wt, *S, *att, *deb;
    cudaGetSymbolAddress((void**)&patchs, g_patchs);
    cudaGetSymbolAddress((void**)&patchx, g_patchx);
    cudaGetSymbolAddress((void**)&h1b,    g_h1b);
    cudaGetSymbolAddress((void**)&q,      g_q);
    cudaGetSymbolAddress((void**)&k,      g_k);
    cudaGetSymbolAddress((void**)&v,      g_v);
    cudaGetSymbolAddress((void**)&Wt,     g_Wt);
    cudaGetSymbolAddress((void**)&S,      g_S);
    cudaGetSymbolAddress((void**)&att,    g_att);
    cudaGetSymbolAddress((void**)&deb,    g_deb);

    // fused LN6 + patch gather (once per input tensor)
    k_patch<<<(NPATCH * 8 + 255) / 256, 256>>>(skip, ns_w, ns_b, patchs);
    k_patch<<<(NPATCH * 8 + 255) / 256, 256>>>(x,    nx_w, nx_b, patchx);

    const float* stem_patch[3] = {patchs, patchx, patchx};
    float* stem_out[3] = {q, k, v};
    int rope[3] = {1, 1, 0};
    for (int si = 0; si < 3; si++) {
        int base = 2 + si * 6;
        const float* w1 = (const float*)d_in[base + 0];
        const float* g1 = (const float*)d_in[base + 1];
        const float* b1 = (const float*)d_in[base + 2];
        const float* w2 = (const float*)d_in[base + 3];
        const float* g2 = (const float*)d_in[base + 4];
        const float* b2 = (const float*)d_in[base + 5];
        // conv1 as GEMM: [27648 x 48] * [48 x 192] -> h1b rows (token*8+par)
        k_transW1<<<(192 * 48 + 255) / 256, 256>>>(w1, Wt);
        dim3 g1g(192 / 64, NPATCH / 64);
        k_gemm64<<<g1g, 256>>>(stem_patch[si], Wt, h1b, 48, 48, 192, 192);
        k_ln192gelu<<<NPATCH, 192>>>(h1b, g1, b1);
        // conv2 as GEMM: h1b is contiguous [3456 x 1536] with K-index par*192+t
        k_transW2<<<(EE * KK2 + 255) / 256, 256>>>(w2, Wt);
        dim3 gg(EE / 64, NTOK / 64);
        k_gemm64<<<gg, 256>>>(h1b, Wt, stem_out[si], KK2, KK2, EE, EE);
        k_ln768<<<NTOK, 256>>>(stem_out[si], g2, b2, rope[si]);
    }

    k_scores<<<dim3(27, 27, 24), 256>>>(q, k, S);
    k_softmax<<<B2 * NH * S12, 256>>>(S);
    k_pv<<<dim3(1, 27, 24), 256>>>(S, v, att);

    k_ln768<<<NTOK, 256>>>(att, no_w, no_b, 0);
    k_transWd<<<(EE * KK2 + 255) / 256, 256>>>(o_tw1, Wt);
    dim3 gd(KK2 / 64, NTOK / 64);
    k_gemm64<<<gd, 256>>>(att, Wt, deb, EE, EE, KK2, KK2);
    k_ln192gelu<<<NTOK * 8, 192>>>(deb, o_g, o_b);
    k_debed2<<<B2 * S24, 64>>>(deb, o_tw2, o_tb2, skip, out);
}